// round 1
// baseline (speedup 1.0000x reference)
#include <cuda_runtime.h>
#include <math.h>

#define NN 100000
#define IN_CH 16
#define HID 128
#define EE 1600000
#define ET (EE + NN)
#define NB 98            // ceil(NN/1024)
#define NEG 0.2f
#define LN_EPS 1e-5f

// ---------------- scratch (static device globals; no allocation) ----------------
__device__ float g_h1[NN * HID];      // layer1 features h1; reused as h2 after gemm2
__device__ float g_hln[NN * HID];     // post ELU+LN features (layer1 output)
__device__ float g_as1[NN * 4];
__device__ float g_ad1[NN * 4];
__device__ float g_as2[NN];
__device__ float g_ad2[NN];
__device__ int   g_deg[NN];
__device__ int   g_scanpart[NN];
__device__ int   g_blocksum[NB];
__device__ int   g_rowptr[NN + 1];
__device__ int   g_cursor[NN];
__device__ int   g_esrc[ET];

__device__ __forceinline__ float sel4(float4 v, int i) {
    float r = v.x;
    r = (i == 1) ? v.y : r;
    r = (i == 2) ? v.z : r;
    r = (i == 3) ? v.w : r;
    return r;
}

__device__ __forceinline__ float lrelu(float e) { return e > 0.f ? e : NEG * e; }

// ---------------- K1: h1 = x @ W1, plus per-head alpha_src / alpha_dst ----------
__global__ void __launch_bounds__(128) k_gemm1(const float* __restrict__ x,
                                               const float* __restrict__ W1,
                                               const float* __restrict__ a_src,
                                               const float* __restrict__ a_dst) {
    int n = blockIdx.x;
    int t = threadIdx.x;           // 0..127, channel
    __shared__ float sx[IN_CH];
    if (t < IN_CH) sx[t] = x[n * IN_CH + t];
    __syncthreads();
    float acc = 0.f;
#pragma unroll
    for (int k = 0; k < IN_CH; k++) acc = fmaf(sx[k], W1[k * HID + t], acc);
    g_h1[n * HID + t] = acc;
    // heads: head = t>>5 == warp id; a_src is [4,32] flat == [128]
    int head = t >> 5, lane = t & 31;
    float ps = acc * a_src[t];
    float pd = acc * a_dst[t];
#pragma unroll
    for (int off = 16; off; off >>= 1) {
        ps += __shfl_xor_sync(0xffffffffu, ps, off);
        pd += __shfl_xor_sync(0xffffffffu, pd, off);
    }
    if (lane == 0) {
        g_as1[n * 4 + head] = ps;
        g_ad1[n * 4 + head] = pd;
    }
}

// ---------------- CSR build: zero, histogram, scan, scatter ---------------------
__global__ void k_zero() {
    int i = blockIdx.x * blockDim.x + threadIdx.x;
    if (i < NN) g_deg[i] = 0;
}

__global__ void k_hist(const int* __restrict__ ei) {
    int e = blockIdx.x * blockDim.x + threadIdx.x;
    if (e < ET) {
        int d = (e < EE) ? ei[EE + e] : (e - EE);
        atomicAdd(&g_deg[d], 1);
    }
}

__global__ void __launch_bounds__(1024) k_scan1() {
    __shared__ int sh[1024];
    int t = threadIdx.x;
    int i = blockIdx.x * 1024 + t;
    int v = (i < NN) ? g_deg[i] : 0;
    sh[t] = v;
    __syncthreads();
#pragma unroll
    for (int off = 1; off < 1024; off <<= 1) {
        int tv = (t >= off) ? sh[t - off] : 0;
        __syncthreads();
        sh[t] += tv;
        __syncthreads();
    }
    if (i < NN) g_scanpart[i] = sh[t] - v;  // exclusive within block
    if (t == 1023) g_blocksum[blockIdx.x] = sh[1023];
}

__global__ void __launch_bounds__(1024) k_scan2() {
    __shared__ int soff;
    int t = threadIdx.x;
    if (t == 0) {
        int s = 0;
        for (int b = 0; b < blockIdx.x; b++) s += g_blocksum[b];
        soff = s;
    }
    __syncthreads();
    int i = blockIdx.x * 1024 + t;
    if (i < NN) {
        int r = g_scanpart[i] + soff;
        g_rowptr[i] = r;
        g_cursor[i] = r;
    }
    if (i == 0) g_rowptr[NN] = ET;
}

__global__ void k_scatter(const int* __restrict__ ei) {
    int e = blockIdx.x * blockDim.x + threadIdx.x;
    if (e < ET) {
        int s, d;
        if (e < EE) { s = ei[e]; d = ei[EE + e]; }
        else        { s = e - EE; d = s; }
        int p = atomicAdd(&g_cursor[d], 1);
        g_esrc[p] = s;
    }
}

// ---------------- K5: layer-1 GAT aggregation + bias + ELU + LayerNorm ----------
__global__ void __launch_bounds__(256) k_agg1(const float* __restrict__ b1,
                                              const float* __restrict__ g1,
                                              const float* __restrict__ bt1) {
    int n = blockIdx.x * 8 + (threadIdx.x >> 5);  // NN divisible by 8
    int lane = threadIdx.x & 31;
    const float4 ad = *(const float4*)&g_ad1[n * 4];
    int start = g_rowptr[n], end = g_rowptr[n + 1];

    // pass 1: softmax denominators per head (edges distributed over lanes)
    float d0 = 0.f, d1 = 0.f, d2 = 0.f, d3 = 0.f;
    for (int j0 = start; j0 < end; j0 += 32) {
        int j = j0 + lane;
        if (j < end) {
            int s = g_esrc[j];
            float4 as = *(const float4*)&g_as1[s * 4];
            d0 += __expf(lrelu(as.x + ad.x));
            d1 += __expf(lrelu(as.y + ad.y));
            d2 += __expf(lrelu(as.z + ad.z));
            d3 += __expf(lrelu(as.w + ad.w));
        }
    }
#pragma unroll
    for (int off = 16; off; off >>= 1) {
        d0 += __shfl_xor_sync(0xffffffffu, d0, off);
        d1 += __shfl_xor_sync(0xffffffffu, d1, off);
        d2 += __shfl_xor_sync(0xffffffffu, d2, off);
        d3 += __shfl_xor_sync(0xffffffffu, d3, off);
    }
    int h = lane >> 3;  // lane handles channels [4*lane,4*lane+4) -> head = lane/8
    float rd  = 1.0f / sel4(make_float4(d0, d1, d2, d3), h);
    float adh = sel4(ad, h);

    // pass 2: weighted aggregation (all lanes walk the edge list together)
    float a0 = 0.f, a1 = 0.f, a2 = 0.f, a3 = 0.f;
#pragma unroll 4
    for (int j = start; j < end; j++) {
        int s = g_esrc[j];
        float as = g_as1[s * 4 + h];
        float w = __expf(lrelu(as + adh)) * rd;
        float4 hv = *(const float4*)&g_h1[s * HID + lane * 4];
        a0 = fmaf(w, hv.x, a0);
        a1 = fmaf(w, hv.y, a1);
        a2 = fmaf(w, hv.z, a2);
        a3 = fmaf(w, hv.w, a3);
    }
    int ch = lane * 4;
    a0 += b1[ch]; a1 += b1[ch + 1]; a2 += b1[ch + 2]; a3 += b1[ch + 3];
    // ELU
    a0 = a0 > 0.f ? a0 : expm1f(a0);
    a1 = a1 > 0.f ? a1 : expm1f(a1);
    a2 = a2 > 0.f ? a2 : expm1f(a2);
    a3 = a3 > 0.f ? a3 : expm1f(a3);
    // LayerNorm over 128 channels (warp reduce)
    float s4 = a0 + a1 + a2 + a3;
#pragma unroll
    for (int off = 16; off; off >>= 1) s4 += __shfl_xor_sync(0xffffffffu, s4, off);
    float mu = s4 * (1.0f / 128.0f);
    float c0 = a0 - mu, c1 = a1 - mu, c2 = a2 - mu, c3 = a3 - mu;
    float v4 = c0 * c0 + c1 * c1 + c2 * c2 + c3 * c3;
#pragma unroll
    for (int off = 16; off; off >>= 1) v4 += __shfl_xor_sync(0xffffffffu, v4, off);
    float inv = rsqrtf(v4 * (1.0f / 128.0f) + LN_EPS);
    float4 o;
    o.x = fmaf(c0 * inv, g1[ch + 0], bt1[ch + 0]);
    o.y = fmaf(c1 * inv, g1[ch + 1], bt1[ch + 1]);
    o.z = fmaf(c2 * inv, g1[ch + 2], bt1[ch + 2]);
    o.w = fmaf(c3 * inv, g1[ch + 3], bt1[ch + 3]);
    *(float4*)&g_hln[n * HID + ch] = o;
}

// ---------------- K6: h2 = hln @ W2 (+ alpha2 dots), W2 in smem, 8-node tile ----
__global__ void __launch_bounds__(128) k_gemm2(const float* __restrict__ W2,
                                               const float* __restrict__ asw,
                                               const float* __restrict__ adw) {
    extern __shared__ float sm[];
    float* sW   = sm;                 // 128*128
    float* srow = sm + 16384;         // 8*128
    float* sred = sm + 16384 + 1024;  // 64
    int t = threadIdx.x;
    for (int i = t; i < 16384; i += 128) sW[i] = W2[i];
    float av = asw[t], dv = adw[t];
    int wid = t >> 5, lane = t & 31;

    for (int n0 = blockIdx.x * 8; n0 < NN; n0 += gridDim.x * 8) {
        __syncthreads();
#pragma unroll
        for (int i = 0; i < 8; i++) srow[i * 128 + t] = g_hln[(n0 + i) * HID + t];
        __syncthreads();
        float acc[8];
#pragma unroll
        for (int j = 0; j < 8; j++) acc[j] = 0.f;
#pragma unroll 4
        for (int k = 0; k < 128; k += 4) {
            float w0 = sW[(k + 0) * 128 + t];
            float w1 = sW[(k + 1) * 128 + t];
            float w2 = sW[(k + 2) * 128 + t];
            float w3 = sW[(k + 3) * 128 + t];
#pragma unroll
            for (int j = 0; j < 8; j++) {
                float4 r = *(const float4*)&srow[j * 128 + k];
                acc[j] = fmaf(r.x, w0, fmaf(r.y, w1, fmaf(r.z, w2, fmaf(r.w, w3, acc[j]))));
            }
        }
#pragma unroll
        for (int j = 0; j < 8; j++) {
            g_h1[(n0 + j) * HID + t] = acc[j];  // reuse g_h1 as h2
            float ps = acc[j] * av, pd = acc[j] * dv;
#pragma unroll
            for (int off = 16; off; off >>= 1) {
                ps += __shfl_xor_sync(0xffffffffu, ps, off);
                pd += __shfl_xor_sync(0xffffffffu, pd, off);
            }
            if (lane == 0) { sred[j * 4 + wid] = ps; sred[32 + j * 4 + wid] = pd; }
        }
        __syncthreads();
        if (t < 16) {
            int j = t >> 1, isd = t & 1;
            const float* p = &sred[isd * 32 + j * 4];
            float sum = p[0] + p[1] + p[2] + p[3];
            if (isd == 0) g_as2[n0 + j] = sum;
            else          g_ad2[n0 + j] = sum;
        }
    }
}

// ---------------- K7: layer-2 GAT aggregation + bias + ELU + LayerNorm -> out ---
__global__ void __launch_bounds__(256) k_agg2(const float* __restrict__ b2,
                                              const float* __restrict__ g2,
                                              const float* __restrict__ bt2,
                                              float* __restrict__ out) {
    int n = blockIdx.x * 8 + (threadIdx.x >> 5);
    int lane = threadIdx.x & 31;
    float adn = g_ad2[n];
    int start = g_rowptr[n], end = g_rowptr[n + 1];

    float den = 0.f;
    for (int j0 = start; j0 < end; j0 += 32) {
        int j = j0 + lane;
        if (j < end) {
            float e = g_as2[g_esrc[j]] + adn;
            den += __expf(lrelu(e));
        }
    }
#pragma unroll
    for (int off = 16; off; off >>= 1) den += __shfl_xor_sync(0xffffffffu, den, off);
    float rd = 1.0f / den;

    float a0 = 0.f, a1 = 0.f, a2 = 0.f, a3 = 0.f;
#pragma unroll 4
    for (int j = start; j < end; j++) {
        int s = g_esrc[j];
        float w = __expf(lrelu(g_as2[s] + adn)) * rd;
        float4 hv = *(const float4*)&g_h1[s * HID + lane * 4];
        a0 = fmaf(w, hv.x, a0);
        a1 = fmaf(w, hv.y, a1);
        a2 = fmaf(w, hv.z, a2);
        a3 = fmaf(w, hv.w, a3);
    }
    int ch = lane * 4;
    a0 += b2[ch]; a1 += b2[ch + 1]; a2 += b2[ch + 2]; a3 += b2[ch + 3];
    a0 = a0 > 0.f ? a0 : expm1f(a0);
    a1 = a1 > 0.f ? a1 : expm1f(a1);
    a2 = a2 > 0.f ? a2 : expm1f(a2);
    a3 = a3 > 0.f ? a3 : expm1f(a3);
    float s4 = a0 + a1 + a2 + a3;
#pragma unroll
    for (int off = 16; off; off >>= 1) s4 += __shfl_xor_sync(0xffffffffu, s4, off);
    float mu = s4 * (1.0f / 128.0f);
    float c0 = a0 - mu, c1 = a1 - mu, c2 = a2 - mu, c3 = a3 - mu;
    float v4 = c0 * c0 + c1 * c1 + c2 * c2 + c3 * c3;
#pragma unroll
    for (int off = 16; off; off >>= 1) v4 += __shfl_xor_sync(0xffffffffu, v4, off);
    float inv = rsqrtf(v4 * (1.0f / 128.0f) + LN_EPS);
    float4 o;
    o.x = fmaf(c0 * inv, g2[ch + 0], bt2[ch + 0]);
    o.y = fmaf(c1 * inv, g2[ch + 1], bt2[ch + 1]);
    o.z = fmaf(c2 * inv, g2[ch + 2], bt2[ch + 2]);
    o.w = fmaf(c3 * inv, g2[ch + 3], bt2[ch + 3]);
    *(float4*)&out[n * HID + ch] = o;
}

// ---------------- launch ----------------
extern "C" void kernel_launch(void* const* d_in, const int* in_sizes, int n_in,
                              void* d_out, int out_size) {
    const float* x     = (const float*)d_in[0];
    const int*   ei    = (const int*)d_in[1];
    const float* W1    = (const float*)d_in[2];
    const float* asr1  = (const float*)d_in[3];
    const float* adt1  = (const float*)d_in[4];
    const float* b1    = (const float*)d_in[5];
    const float* g1    = (const float*)d_in[6];
    const float* bt1   = (const float*)d_in[7];
    const float* W2    = (const float*)d_in[8];
    const float* asr2  = (const float*)d_in[9];
    const float* adt2  = (const float*)d_in[10];
    const float* b2    = (const float*)d_in[11];
    const float* g2    = (const float*)d_in[12];
    const float* bt2   = (const float*)d_in[13];
    float* out = (float*)d_out;

    const int SMEM2 = (16384 + 1024 + 128) * sizeof(float);
    cudaFuncSetAttribute(k_gemm2, cudaFuncAttributeMaxDynamicSharedMemorySize, SMEM2);

    k_gemm1<<<NN, 128>>>(x, W1, asr1, adt1);
    k_zero<<<(NN + 255) / 256, 256>>>();
    k_hist<<<(ET + 255) / 256, 256>>>(ei);
    k_scan1<<<NB, 1024>>>();
    k_scan2<<<NB, 1024>>>();
    k_scatter<<<(ET + 255) / 256, 256>>>(ei);
    k_agg1<<<NN / 8, 256>>>(b1, g1, bt1);
    k_gemm2<<<444, 128, SMEM2>>>(W2, asr2, adt2);
    k_agg2<<<NN / 8, 256>>>(b2, g2, bt2, out);
}

// round 2
// speedup vs baseline: 1.0445x; 1.0445x over previous
#include <cuda_runtime.h>
#include <cuda_fp16.h>
#include <math.h>

#define NN 100000
#define IN_CH 16
#define HID 128
#define EE 1600000
#define ET (EE + NN)
#define NB 98            // ceil(NN/1024)
#define NEG 0.2f
#define LN_EPS 1e-5f

// ---------------- scratch (static device globals; no allocation) ----------------
__device__ __half g_h1h[NN * HID];    // layer1 features (fp16, gather target)
__device__ __half g_h2h[NN * HID];    // layer2 features (fp16, gather target)
__device__ float  g_hln[NN * HID];    // post ELU+LN features (fp32, gemm2 input)
__device__ float  g_as1[NN * 4];
__device__ float  g_ad1[NN * 4];
__device__ float  g_as2[NN];
__device__ float  g_ad2[NN];
__device__ int    g_deg[NN];
__device__ int    g_scanpart[NN];
__device__ int    g_blocksum[NB];
__device__ int    g_rowptr[NN + 1];
__device__ int    g_cursor[NN];
__device__ int    g_esrc[ET];

__device__ __forceinline__ float lrelu(float e) { return e > 0.f ? e : NEG * e; }

// ---------------- K1: h1 = x @ W1 (store fp16), + per-head alpha dots -----------
__global__ void __launch_bounds__(128) k_gemm1(const float* __restrict__ x,
                                               const float* __restrict__ W1,
                                               const float* __restrict__ a_src,
                                               const float* __restrict__ a_dst) {
    int n = blockIdx.x;
    int t = threadIdx.x;           // 0..127, output channel
    __shared__ float sx[IN_CH];
    if (t < IN_CH) sx[t] = x[n * IN_CH + t];
    __syncthreads();
    float acc = 0.f;
#pragma unroll
    for (int k = 0; k < IN_CH; k++) acc = fmaf(sx[k], W1[k * HID + t], acc);
    g_h1h[n * HID + t] = __float2half_rn(acc);
    int head = t >> 5, lane = t & 31;
    float ps = acc * a_src[t];
    float pd = acc * a_dst[t];
#pragma unroll
    for (int off = 16; off; off >>= 1) {
        ps += __shfl_xor_sync(0xffffffffu, ps, off);
        pd += __shfl_xor_sync(0xffffffffu, pd, off);
    }
    if (lane == 0) {
        g_as1[n * 4 + head] = ps;
        g_ad1[n * 4 + head] = pd;
    }
}

// ---------------- CSR build: zero, histogram, scan, scatter ---------------------
__global__ void k_zero() {
    int i = blockIdx.x * blockDim.x + threadIdx.x;
    if (i < NN) g_deg[i] = 0;
}

__global__ void k_hist(const int* __restrict__ ei) {
    int e = blockIdx.x * blockDim.x + threadIdx.x;
    if (e < ET) {
        int d = (e < EE) ? ei[EE + e] : (e - EE);
        atomicAdd(&g_deg[d], 1);
    }
}

__global__ void __launch_bounds__(1024) k_scan1() {
    __shared__ int sh[1024];
    int t = threadIdx.x;
    int i = blockIdx.x * 1024 + t;
    int v = (i < NN) ? g_deg[i] : 0;
    sh[t] = v;
    __syncthreads();
#pragma unroll
    for (int off = 1; off < 1024; off <<= 1) {
        int tv = (t >= off) ? sh[t - off] : 0;
        __syncthreads();
        sh[t] += tv;
        __syncthreads();
    }
    if (i < NN) g_scanpart[i] = sh[t] - v;  // exclusive within block
    if (t == 1023) g_blocksum[blockIdx.x] = sh[1023];
}

__global__ void __launch_bounds__(1024) k_scan2() {
    __shared__ int soff;
    int t = threadIdx.x;
    if (t == 0) {
        int s = 0;
        for (int b = 0; b < blockIdx.x; b++) s += g_blocksum[b];
        soff = s;
    }
    __syncthreads();
    int i = blockIdx.x * 1024 + t;
    if (i < NN) {
        int r = g_scanpart[i] + soff;
        g_rowptr[i] = r;
        g_cursor[i] = r;
    }
    if (i == 0) g_rowptr[NN] = ET;
}

__global__ void k_scatter(const int* __restrict__ ei) {
    int e = blockIdx.x * blockDim.x + threadIdx.x;
    if (e < ET) {
        int s, d;
        if (e < EE) { s = ei[e]; d = ei[EE + e]; }
        else        { s = e - EE; d = s; }
        int p = atomicAdd(&g_cursor[d], 1);
        g_esrc[p] = s;
    }
}

// ---------------- K5: layer-1 GAT agg (single pass) + bias + ELU + LN -----------
__global__ void __launch_bounds__(256) k_agg1(const float* __restrict__ b1,
                                              const float* __restrict__ g1,
                                              const float* __restrict__ bt1) {
    int n = blockIdx.x * 8 + (threadIdx.x >> 5);  // NN divisible by 8
    int lane = threadIdx.x & 31;
    int h = lane >> 3;                   // lane handles channels [4*lane, 4*lane+4)
    float adh = g_ad1[n * 4 + h];
    int start = g_rowptr[n], end = g_rowptr[n + 1];

    // single pass: unnormalized weighted sum + denominator (identical across head group)
    float den = 0.f;
    float a0 = 0.f, a1 = 0.f, a2 = 0.f, a3 = 0.f;
#pragma unroll 4
    for (int j = start; j < end; j++) {
        int s = g_esrc[j];
        float as = __ldg(&g_as1[s * 4 + h]);
        float w = __expf(lrelu(as + adh));
        den += w;
        float2 raw = *(const float2*)&g_h1h[s * HID + lane * 4];
        __half2 p01 = *(__half2*)&raw.x;
        __half2 p23 = *(__half2*)&raw.y;
        float2 f01 = __half22float2(p01);
        float2 f23 = __half22float2(p23);
        a0 = fmaf(w, f01.x, a0);
        a1 = fmaf(w, f01.y, a1);
        a2 = fmaf(w, f23.x, a2);
        a3 = fmaf(w, f23.y, a3);
    }
    float rd = 1.0f / den;
    a0 *= rd; a1 *= rd; a2 *= rd; a3 *= rd;

    int ch = lane * 4;
    a0 += b1[ch]; a1 += b1[ch + 1]; a2 += b1[ch + 2]; a3 += b1[ch + 3];
    // ELU
    a0 = a0 > 0.f ? a0 : expm1f(a0);
    a1 = a1 > 0.f ? a1 : expm1f(a1);
    a2 = a2 > 0.f ? a2 : expm1f(a2);
    a3 = a3 > 0.f ? a3 : expm1f(a3);
    // LayerNorm over 128 channels (warp reduce)
    float s4 = a0 + a1 + a2 + a3;
#pragma unroll
    for (int off = 16; off; off >>= 1) s4 += __shfl_xor_sync(0xffffffffu, s4, off);
    float mu = s4 * (1.0f / 128.0f);
    float c0 = a0 - mu, c1 = a1 - mu, c2 = a2 - mu, c3 = a3 - mu;
    float v4 = c0 * c0 + c1 * c1 + c2 * c2 + c3 * c3;
#pragma unroll
    for (int off = 16; off; off >>= 1) v4 += __shfl_xor_sync(0xffffffffu, v4, off);
    float inv = rsqrtf(v4 * (1.0f / 128.0f) + LN_EPS);
    float4 o;
    o.x = fmaf(c0 * inv, g1[ch + 0], bt1[ch + 0]);
    o.y = fmaf(c1 * inv, g1[ch + 1], bt1[ch + 1]);
    o.z = fmaf(c2 * inv, g1[ch + 2], bt1[ch + 2]);
    o.w = fmaf(c3 * inv, g1[ch + 3], bt1[ch + 3]);
    *(float4*)&g_hln[n * HID + ch] = o;
}

// ---------------- K6: h2 = hln @ W2 (+ alpha2 dots), W2 in smem, 8-node tile ----
__global__ void __launch_bounds__(128) k_gemm2(const float* __restrict__ W2,
                                               const float* __restrict__ asw,
                                               const float* __restrict__ adw) {
    extern __shared__ float sm[];
    float* sW   = sm;                 // 128*128
    float* srow = sm + 16384;         // 8*128
    float* sred = sm + 16384 + 1024;  // 64
    int t = threadIdx.x;
    for (int i = t; i < 16384; i += 128) sW[i] = W2[i];
    float av = asw[t], dv = adw[t];
    int wid = t >> 5, lane = t & 31;

    for (int n0 = blockIdx.x * 8; n0 < NN; n0 += gridDim.x * 8) {
        __syncthreads();
#pragma unroll
        for (int i = 0; i < 8; i++) srow[i * 128 + t] = g_hln[(n0 + i) * HID + t];
        __syncthreads();
        float acc[8];
#pragma unroll
        for (int j = 0; j < 8; j++) acc[j] = 0.f;
#pragma unroll 4
        for (int k = 0; k < 128; k += 4) {
            float w0 = sW[(k + 0) * 128 + t];
            float w1 = sW[(k + 1) * 128 + t];
            float w2 = sW[(k + 2) * 128 + t];
            float w3 = sW[(k + 3) * 128 + t];
#pragma unroll
            for (int j = 0; j < 8; j++) {
                float4 r = *(const float4*)&srow[j * 128 + k];
                acc[j] = fmaf(r.x, w0, fmaf(r.y, w1, fmaf(r.z, w2, fmaf(r.w, w3, acc[j]))));
            }
        }
#pragma unroll
        for (int j = 0; j < 8; j++) {
            g_h2h[(n0 + j) * HID + t] = __float2half_rn(acc[j]);
            float ps = acc[j] * av, pd = acc[j] * dv;
#pragma unroll
            for (int off = 16; off; off >>= 1) {
                ps += __shfl_xor_sync(0xffffffffu, ps, off);
                pd += __shfl_xor_sync(0xffffffffu, pd, off);
            }
            if (lane == 0) { sred[j * 4 + wid] = ps; sred[32 + j * 4 + wid] = pd; }
        }
        __syncthreads();
        if (t < 16) {
            int j = t >> 1, isd = t & 1;
            const float* p = &sred[isd * 32 + j * 4];
            float sum = p[0] + p[1] + p[2] + p[3];
            if (isd == 0) g_as2[n0 + j] = sum;
            else          g_ad2[n0 + j] = sum;
        }
    }
}

// ---------------- K7: layer-2 GAT agg (single pass) + bias + ELU + LN -> out ----
__global__ void __launch_bounds__(256) k_agg2(const float* __restrict__ b2,
                                              const float* __restrict__ g2,
                                              const float* __restrict__ bt2,
                                              float* __restrict__ out) {
    int n = blockIdx.x * 8 + (threadIdx.x >> 5);
    int lane = threadIdx.x & 31;
    float adn = g_ad2[n];
    int start = g_rowptr[n], end = g_rowptr[n + 1];

    float den = 0.f;
    float a0 = 0.f, a1 = 0.f, a2 = 0.f, a3 = 0.f;
#pragma unroll 4
    for (int j = start; j < end; j++) {
        int s = g_esrc[j];
        float as = __ldg(&g_as2[s]);
        float w = __expf(lrelu(as + adn));
        den += w;
        float2 raw = *(const float2*)&g_h2h[s * HID + lane * 4];
        __half2 p01 = *(__half2*)&raw.x;
        __half2 p23 = *(__half2*)&raw.y;
        float2 f01 = __half22float2(p01);
        float2 f23 = __half22float2(p23);
        a0 = fmaf(w, f01.x, a0);
        a1 = fmaf(w, f01.y, a1);
        a2 = fmaf(w, f23.x, a2);
        a3 = fmaf(w, f23.y, a3);
    }
    float rd = 1.0f / den;
    a0 *= rd; a1 *= rd; a2 *= rd; a3 *= rd;

    int ch = lane * 4;
    a0 += b2[ch]; a1 += b2[ch + 1]; a2 += b2[ch + 2]; a3 += b2[ch + 3];
    a0 = a0 > 0.f ? a0 : expm1f(a0);
    a1 = a1 > 0.f ? a1 : expm1f(a1);
    a2 = a2 > 0.f ? a2 : expm1f(a2);
    a3 = a3 > 0.f ? a3 : expm1f(a3);
    float s4 = a0 + a1 + a2 + a3;
#pragma unroll
    for (int off = 16; off; off >>= 1) s4 += __shfl_xor_sync(0xffffffffu, s4, off);
    float mu = s4 * (1.0f / 128.0f);
    float c0 = a0 - mu, c1 = a1 - mu, c2 = a2 - mu, c3 = a3 - mu;
    float v4 = c0 * c0 + c1 * c1 + c2 * c2 + c3 * c3;
#pragma unroll
    for (int off = 16; off; off >>= 1) v4 += __shfl_xor_sync(0xffffffffu, v4, off);
    float inv = rsqrtf(v4 * (1.0f / 128.0f) + LN_EPS);
    float4 o;
    o.x = fmaf(c0 * inv, g2[ch + 0], bt2[ch + 0]);
    o.y = fmaf(c1 * inv, g2[ch + 1], bt2[ch + 1]);
    o.z = fmaf(c2 * inv, g2[ch + 2], bt2[ch + 2]);
    o.w = fmaf(c3 * inv, g2[ch + 3], bt2[ch + 3]);
    *(float4*)&out[n * HID + ch] = o;
}

// ---------------- launch ----------------
extern "C" void kernel_launch(void* const* d_in, const int* in_sizes, int n_in,
                              void* d_out, int out_size) {
    const float* x     = (const float*)d_in[0];
    const int*   ei    = (const int*)d_in[1];
    const float* W1    = (const float*)d_in[2];
    const float* asr1  = (const float*)d_in[3];
    const float* adt1  = (const float*)d_in[4];
    const float* b1    = (const float*)d_in[5];
    const float* g1    = (const float*)d_in[6];
    const float* bt1   = (const float*)d_in[7];
    const float* W2    = (const float*)d_in[8];
    const float* asr2  = (const float*)d_in[9];
    const float* adt2  = (const float*)d_in[10];
    const float* b2    = (const float*)d_in[11];
    const float* g2    = (const float*)d_in[12];
    const float* bt2   = (const float*)d_in[13];
    float* out = (float*)d_out;

    const int SMEM2 = (16384 + 1024 + 128) * sizeof(float);
    cudaFuncSetAttribute(k_gemm2, cudaFuncAttributeMaxDynamicSharedMemorySize, SMEM2);

    k_gemm1<<<NN, 128>>>(x, W1, asr1, adt1);
    k_zero<<<(NN + 255) / 256, 256>>>();
    k_hist<<<(ET + 255) / 256, 256>>>(ei);
    k_scan1<<<NB, 1024>>>();
    k_scan2<<<NB, 1024>>>();
    k_scatter<<<(ET + 255) / 256, 256>>>(ei);
    k_agg1<<<NN / 8, 256>>>(b1, g1, bt1);
    k_gemm2<<<444, 128, SMEM2>>>(W2, asr2, adt2);
    k_agg2<<<NN / 8, 256>>>(b2, g2, bt2, out);
}